// round 2
// baseline (speedup 1.0000x reference)
#include <cuda_runtime.h>
#include <cstdint>

#define C_PAD   1024      // classes padded to power of two (real C = 1000)
#define B_ROWS  16384
#define DIN     1024
#define DOUT    256

// ---------------- scratch (static __device__, no allocation) ----------------
__device__ __align__(16) float g_class_sum[C_PAD * DIN];   // 4 MB
__device__ float g_cnt[C_PAD];
__device__ float g_total[DIN];
__device__ __align__(16) float g_M2[C_PAD * DOUT];         // 1 MB
__device__ int   g_lbl_is64;

// ---------------- label dtype handling --------------------------------------
__device__ __forceinline__ int load_label(const void* l, int i, int is64) {
    if (is64) return (int)(((const long long*)l)[i]);
    return ((const int*)l)[i];
}

// K1: zero class sums / counts, assume int64 until disproven
__global__ void k_zero() {
    int i = blockIdx.x * blockDim.x + threadIdx.x;
    int stride = gridDim.x * blockDim.x;
    for (int j = i; j < C_PAD * DIN; j += stride) g_class_sum[j] = 0.f;
    for (int j = i; j < C_PAD; j += stride) g_cnt[j] = 0.f;
    if (i == 0) g_lbl_is64 = 1;
}

// K1b: if labels are int32, the odd 32-bit words are random labels (mostly
// nonzero); if int64, they are high halves == 0. Only scan first 8192 pairs so
// we never read past a 16384-int32 buffer.
__global__ void k_detect(const int* __restrict__ lw) {
    int i = blockIdx.x * blockDim.x + threadIdx.x;
    if (i < B_ROWS / 2) {
        if (lw[2 * i + 1] != 0) g_lbl_is64 = 0;
    }
}

// K2: segment-sum x into g_class_sum via float4 global reductions.
// One block per row; 256 threads x float4 = 1024 floats.
__global__ void k_scatter(const float* __restrict__ x, const void* __restrict__ lbl) {
    int row = blockIdx.x;
    int is64 = g_lbl_is64;
    int c = load_label(lbl, row, is64);
    const float4* xr = (const float4*)(x + (size_t)row * DIN);
    float4 v = xr[threadIdx.x];
    float4* dst = (float4*)(g_class_sum + (size_t)c * DIN);
    atomicAdd(dst + threadIdx.x, v);
    if (threadIdx.x == 0) atomicAdd(&g_cnt[c], 1.0f);
}

// K3: total_sum over classes (4 MB read). 16 blocks x 256 threads:
// block = 64 columns, 4-way class split + smem reduce.
__global__ void k_total() {
    int col  = blockIdx.x * 64 + (threadIdx.x & 63);
    int part = threadIdx.x >> 6;              // 0..3, 256 classes each
    float s = 0.f;
    int c0 = part * (C_PAD / 4);
#pragma unroll 4
    for (int c = c0; c < c0 + C_PAD / 4; ++c) s += g_class_sum[(size_t)c * DIN + col];
    __shared__ float red[256];
    red[threadIdx.x] = s;
    __syncthreads();
    if (part == 0)
        g_total[col] = red[threadIdx.x] + red[threadIdx.x + 64] +
                       red[threadIdx.x + 128] + red[threadIdx.x + 192];
}

// K4: M2[c] = ((total - class_sum[c]) * scale_c) @ W2^T + b2
// Tiled fp32 GEMM: BM=32 (classes) x BN=64 x BK=32, 256 threads, 2x4 per thread.
// grid = (DOUT/64, C_PAD/32) = (4, 32)
__global__ __launch_bounds__(256) void k_m2(const float* __restrict__ W2w,
                                            const float* __restrict__ W2b) {
    __shared__ float As[32][33];   // [k][m]
    __shared__ float Bs[32][68];   // [k][n], padded (68*4B keeps 16B alignment)
    __shared__ float sscale[32];

    int n0 = blockIdx.x * 64;
    int c0 = blockIdx.y * 32;
    int tid = threadIdx.x;

    if (tid < 32) {
        float cnt = g_cnt[c0 + tid];
        float oc = (float)B_ROWS - cnt;
        sscale[tid] = (oc > 0.5f) ? (1.0f / oc) : 0.0f;
    }
    __syncthreads();

    int am = tid >> 3;             // 0..31 class row
    int ak = (tid & 7) * 4;        // k offset (float4)
    int tx = tid & 15, ty = tid >> 4;
    float acc[2][4] = {};

    for (int k0 = 0; k0 < DIN; k0 += 32) {
        // load A tile: mean values on the fly
        float4 t4 = *(const float4*)(g_total + k0 + ak);
        float4 s4 = *(const float4*)(g_class_sum + (size_t)(c0 + am) * DIN + k0 + ak);
        float sc = sscale[am];
        __syncthreads();
        As[ak + 0][am] = (t4.x - s4.x) * sc;
        As[ak + 1][am] = (t4.y - s4.y) * sc;
        As[ak + 2][am] = (t4.z - s4.z) * sc;
        As[ak + 3][am] = (t4.w - s4.w) * sc;
        // load B tile: W2 rows (n) along k
#pragma unroll
        for (int it = 0; it < 2; ++it) {
            int idx = tid + it * 256;
            int bn = idx >> 3;
            int bk = (idx & 7) * 4;
            float4 w4 = *(const float4*)(W2w + (size_t)(n0 + bn) * DIN + k0 + bk);
            Bs[bk + 0][bn] = w4.x;
            Bs[bk + 1][bn] = w4.y;
            Bs[bk + 2][bn] = w4.z;
            Bs[bk + 3][bn] = w4.w;
        }
        __syncthreads();
#pragma unroll
        for (int k = 0; k < 32; ++k) {
            float a0 = As[k][2 * ty + 0];
            float a1 = As[k][2 * ty + 1];
            float4 b = *(const float4*)(&Bs[k][4 * tx]);
            acc[0][0] += a0 * b.x; acc[0][1] += a0 * b.y;
            acc[0][2] += a0 * b.z; acc[0][3] += a0 * b.w;
            acc[1][0] += a1 * b.x; acc[1][1] += a1 * b.y;
            acc[1][2] += a1 * b.z; acc[1][3] += a1 * b.w;
        }
    }
#pragma unroll
    for (int r = 0; r < 2; ++r) {
        int c = c0 + 2 * ty + r;
        int n = n0 + 4 * tx;
        float4 bb = *(const float4*)(W2b + n);
        float4 o;
        o.x = acc[r][0] + bb.x; o.y = acc[r][1] + bb.y;
        o.z = acc[r][2] + bb.z; o.w = acc[r][3] + bb.w;
        *(float4*)(g_M2 + (size_t)c * DOUT + n) = o;
    }
}

// K5: out = x @ W1^T + b1 + M2[label]
// BM=128, BN=128, BK=8, 256 threads, 8x8 per thread. grid = (2, 128)
__global__ __launch_bounds__(256, 2) void k_main(const float* __restrict__ x,
                                                 const void* __restrict__ lbl,
                                                 const float* __restrict__ W1w,
                                                 const float* __restrict__ W1b,
                                                 float* __restrict__ out) {
    __shared__ float As[8][128];
    __shared__ float Bs[8][128];

    int n0 = blockIdx.x * 128;
    int m0 = blockIdx.y * 128;
    int tid = threadIdx.x;

    int lr = tid >> 1;            // 0..127
    int lk = (tid & 1) * 4;       // 0 or 4
    const float* xg = x   + (size_t)(m0 + lr) * DIN + lk;
    const float* wg = W1w + (size_t)(n0 + lr) * DIN + lk;

    int tx = tid & 15, ty = tid >> 4;   // 16 x 16 thread grid, 8x8 each
    float acc[8][8] = {};

    for (int k0 = 0; k0 < DIN; k0 += 8) {
        float4 av = *(const float4*)(xg + k0);
        float4 bv = *(const float4*)(wg + k0);
        __syncthreads();
        As[lk + 0][lr] = av.x; As[lk + 1][lr] = av.y;
        As[lk + 2][lr] = av.z; As[lk + 3][lr] = av.w;
        Bs[lk + 0][lr] = bv.x; Bs[lk + 1][lr] = bv.y;
        Bs[lk + 2][lr] = bv.z; Bs[lk + 3][lr] = bv.w;
        __syncthreads();
#pragma unroll
        for (int k = 0; k < 8; ++k) {
            float a[8], b[8];
            *(float4*)(a)     = *(const float4*)(&As[k][ty * 8]);
            *(float4*)(a + 4) = *(const float4*)(&As[k][ty * 8 + 4]);
            *(float4*)(b)     = *(const float4*)(&Bs[k][tx * 8]);
            *(float4*)(b + 4) = *(const float4*)(&Bs[k][tx * 8 + 4]);
#pragma unroll
            for (int i = 0; i < 8; ++i)
#pragma unroll
                for (int j = 0; j < 8; ++j)
                    acc[i][j] += a[i] * b[j];
        }
    }

    // epilogue: + b1[n] + M2[label[m]][n]
    int is64 = g_lbl_is64;
    int nq = tx * 2;  // float4 index within 128-wide tile
    const float4* b1r = (const float4*)(W1b + n0);
    float4 bb0 = b1r[nq], bb1 = b1r[nq + 1];
#pragma unroll
    for (int i = 0; i < 8; ++i) {
        int m = m0 + ty * 8 + i;
        int c = load_label(lbl, m, is64);
        const float4* m2r = (const float4*)(g_M2 + (size_t)c * DOUT + n0);
        float4 mm0 = m2r[nq], mm1 = m2r[nq + 1];
        float4 o0, o1;
        o0.x = acc[i][0] + bb0.x + mm0.x;
        o0.y = acc[i][1] + bb0.y + mm0.y;
        o0.z = acc[i][2] + bb0.z + mm0.z;
        o0.w = acc[i][3] + bb0.w + mm0.w;
        o1.x = acc[i][4] + bb1.x + mm1.x;
        o1.y = acc[i][5] + bb1.y + mm1.y;
        o1.z = acc[i][6] + bb1.z + mm1.z;
        o1.w = acc[i][7] + bb1.w + mm1.w;
        float4* op = (float4*)(out + (size_t)m * DOUT + n0);
        op[nq]     = o0;
        op[nq + 1] = o1;
    }
}

// ---------------- launch ----------------------------------------------------
extern "C" void kernel_launch(void* const* d_in, const int* in_sizes, int n_in,
                              void* d_out, int out_size) {
    const float* x   = (const float*)d_in[0];
    const void*  lbl = d_in[1];                 // int64 or int32, detected on device
    const float* W1w = (const float*)d_in[2];
    const float* W1b = (const float*)d_in[3];
    const float* W2w = (const float*)d_in[4];
    const float* W2b = (const float*)d_in[5];
    float* out = (float*)d_out;

    k_zero<<<512, 256>>>();
    k_detect<<<32, 256>>>((const int*)lbl);
    k_scatter<<<B_ROWS, 256>>>(x, lbl);
    k_total<<<16, 256>>>();
    k_m2<<<dim3(4, 32), 256>>>(W2w, W2b);
    k_main<<<dim3(2, 128), 256>>>(x, lbl, W1w, W1b, out);
}

// round 4
// speedup vs baseline: 1.5695x; 1.5695x over previous
#include <cuda_runtime.h>
#include <cuda_bf16.h>
#include <cstdint>

#define C_PAD   1024
#define B_ROWS  16384
#define DIN     1024
#define DOUT    256

// ---------------- scratch (static __device__, no allocation) ----------------
__device__ __align__(16) float g_class_sum[C_PAD * DIN];   // 4 MB
__device__ float g_cnt[C_PAD];
__device__ float g_total[DIN];
__device__ __align__(16) float g_M2[C_PAD * DOUT];         // 1 MB
__device__ int   g_lbl_is64;

// ---------------- label dtype handling --------------------------------------
__device__ __forceinline__ int load_label(const void* l, int i, int is64) {
    if (is64) return (int)(((const long long*)l)[i]);
    return ((const int*)l)[i];
}

// ---------------- small kernels ---------------------------------------------
__global__ void k_zero() {
    int i = blockIdx.x * blockDim.x + threadIdx.x;
    int stride = gridDim.x * blockDim.x;
    for (int j = i; j < C_PAD * DIN; j += stride) g_class_sum[j] = 0.f;
    for (int j = i; j < C_PAD; j += stride) g_cnt[j] = 0.f;
    for (int j = i; j < DIN; j += stride) g_total[j] = 0.f;
    if (i == 0) g_lbl_is64 = 1;
}

// int64 labels have all-zero high words; int32 labels make odd words nonzero
__global__ void k_detect(const int* __restrict__ lw) {
    int i = blockIdx.x * blockDim.x + threadIdx.x;
    if (i < B_ROWS / 2) {
        if (lw[2 * i + 1] != 0) g_lbl_is64 = 0;
    }
}

// segment-sum x by label (float4 global REDs)
__global__ void k_scatter(const float* __restrict__ x, const void* __restrict__ lbl) {
    int row = blockIdx.x;
    int is64 = g_lbl_is64;
    int c = load_label(lbl, row, is64);
    const float4* xr = (const float4*)(x + (size_t)row * DIN);
    float4 v = xr[threadIdx.x];
    float4* dst = (float4*)(g_class_sum + (size_t)c * DIN);
    atomicAdd(dst + threadIdx.x, v);
    if (threadIdx.x == 0) atomicAdd(&g_cnt[c], 1.0f);
}

// total_sum over classes. grid (16,16): x = 64-col block, y = 64-class block.
__global__ void k_total() {
    int col  = blockIdx.x * 64 + (threadIdx.x & 63);
    int part = threadIdx.x >> 6;                       // 0..3 -> 16 classes each
    int c0 = blockIdx.y * 64 + part * 16;
    float s = 0.f;
#pragma unroll
    for (int c = c0; c < c0 + 16; ++c) s += g_class_sum[(size_t)c * DIN + col];
    __shared__ float red[256];
    red[threadIdx.x] = s;
    __syncthreads();
    if (part == 0)
        atomicAdd(&g_total[col], red[threadIdx.x] + red[threadIdx.x + 64] +
                                 red[threadIdx.x + 128] + red[threadIdx.x + 192]);
}

// M2[c] = mean_c @ W2^T + b2  (fp32 tiled GEMM, small)
__global__ __launch_bounds__(256) void k_m2(const float* __restrict__ W2w,
                                            const float* __restrict__ W2b) {
    __shared__ float As[32][33];
    __shared__ float Bs[32][68];
    __shared__ float sscale[32];

    int n0 = blockIdx.x * 64;
    int c0 = blockIdx.y * 32;
    int tid = threadIdx.x;

    if (tid < 32) {
        float cnt = g_cnt[c0 + tid];
        float oc = (float)B_ROWS - cnt;
        sscale[tid] = (oc > 0.5f) ? (1.0f / oc) : 0.0f;
    }
    __syncthreads();

    int am = tid >> 3;
    int ak = (tid & 7) * 4;
    int tx = tid & 15, ty = tid >> 4;
    float acc[2][4] = {};

    for (int k0 = 0; k0 < DIN; k0 += 32) {
        float4 t4 = *(const float4*)(g_total + k0 + ak);
        float4 s4 = *(const float4*)(g_class_sum + (size_t)(c0 + am) * DIN + k0 + ak);
        float sc = sscale[am];
        __syncthreads();
        As[ak + 0][am] = (t4.x - s4.x) * sc;
        As[ak + 1][am] = (t4.y - s4.y) * sc;
        As[ak + 2][am] = (t4.z - s4.z) * sc;
        As[ak + 3][am] = (t4.w - s4.w) * sc;
#pragma unroll
        for (int it = 0; it < 2; ++it) {
            int idx = tid + it * 256;
            int bn = idx >> 3;
            int bk = (idx & 7) * 4;
            float4 w4 = *(const float4*)(W2w + (size_t)(n0 + bn) * DIN + k0 + bk);
            Bs[bk + 0][bn] = w4.x;
            Bs[bk + 1][bn] = w4.y;
            Bs[bk + 2][bn] = w4.z;
            Bs[bk + 3][bn] = w4.w;
        }
        __syncthreads();
#pragma unroll
        for (int k = 0; k < 32; ++k) {
            float a0 = As[k][2 * ty + 0];
            float a1 = As[k][2 * ty + 1];
            float4 b = *(const float4*)(&Bs[k][4 * tx]);
            acc[0][0] += a0 * b.x; acc[0][1] += a0 * b.y;
            acc[0][2] += a0 * b.z; acc[0][3] += a0 * b.w;
            acc[1][0] += a1 * b.x; acc[1][1] += a1 * b.y;
            acc[1][2] += a1 * b.z; acc[1][3] += a1 * b.w;
        }
    }
#pragma unroll
    for (int r = 0; r < 2; ++r) {
        int c = c0 + 2 * ty + r;
        int n = n0 + 4 * tx;
        float4 bb = *(const float4*)(W2b + n);
        float4 o;
        o.x = acc[r][0] + bb.x; o.y = acc[r][1] + bb.y;
        o.z = acc[r][2] + bb.z; o.w = acc[r][3] + bb.w;
        *(float4*)(g_M2 + (size_t)c * DOUT + n) = o;
    }
}

// ---------------- k_main: mma.sync bf16 3-term split GEMM --------------------
// out[16384,256] = x @ W1^T + b1 + M2[label]
// x = xh + xl (bf16 split), W = wh + wl; D = xh@wh + xh@wl + xl@wh.
// CTA tile: M=128, N=256 (full). 8 warps: 2 (M) x 4 (N), 64x64 per warp.
// K chunks of 32. Shared: A/B hi+lo, row stride 40 bf16 (80B, conflict-free).

#define KC      32              // k-chunk
#define A_STRIDE 40             // bf16 elems per smem row
#define SM_AH   0
#define SM_AL   (128 * A_STRIDE * 2)                 // 10240
#define SM_BH   (2 * 128 * A_STRIDE * 2)             // 20480
#define SM_BL   (SM_BH + 256 * A_STRIDE * 2)         // 40960
#define SM_TOT  (SM_BH + 2 * 256 * A_STRIDE * 2)     // 61440

__device__ __forceinline__ uint32_t smem_u32(const void* p) {
    uint32_t a;
    asm("{ .reg .u64 t; cvta.to.shared.u64 t, %1; cvt.u32.u64 %0, t; }" : "=r"(a) : "l"(p));
    return a;
}

__device__ __forceinline__ void ldsm_x4(uint32_t addr, uint32_t* r) {
    asm volatile("ldmatrix.sync.aligned.m8n8.x4.shared.b16 {%0,%1,%2,%3}, [%4];"
                 : "=r"(r[0]), "=r"(r[1]), "=r"(r[2]), "=r"(r[3]) : "r"(addr));
}
__device__ __forceinline__ void ldsm_x2(uint32_t addr, uint32_t* r) {
    asm volatile("ldmatrix.sync.aligned.m8n8.x2.shared.b16 {%0,%1}, [%2];"
                 : "=r"(r[0]), "=r"(r[1]) : "r"(addr));
}
__device__ __forceinline__ void mma_bf16(float* c, const uint32_t* a, const uint32_t* b) {
    asm volatile(
        "mma.sync.aligned.m16n8k16.row.col.f32.bf16.bf16.f32 "
        "{%0,%1,%2,%3}, {%4,%5,%6,%7}, {%8,%9}, {%0,%1,%2,%3};"
        : "+f"(c[0]), "+f"(c[1]), "+f"(c[2]), "+f"(c[3])
        : "r"(a[0]), "r"(a[1]), "r"(a[2]), "r"(a[3]), "r"(b[0]), "r"(b[1]));
}

// convert float4 -> packed bf16 hi (uint2) and residual lo (uint2)
__device__ __forceinline__ void split4(float4 v, uint2& hi, uint2& lo) {
    __nv_bfloat162 h01 = __floats2bfloat162_rn(v.x, v.y);
    __nv_bfloat162 h23 = __floats2bfloat162_rn(v.z, v.w);
    float r0 = v.x - __bfloat162float(h01.x);
    float r1 = v.y - __bfloat162float(h01.y);
    float r2 = v.z - __bfloat162float(h23.x);
    float r3 = v.w - __bfloat162float(h23.y);
    __nv_bfloat162 l01 = __floats2bfloat162_rn(r0, r1);
    __nv_bfloat162 l23 = __floats2bfloat162_rn(r2, r3);
    hi.x = *(uint32_t*)&h01; hi.y = *(uint32_t*)&h23;
    lo.x = *(uint32_t*)&l01; lo.y = *(uint32_t*)&l23;
}

__global__ __launch_bounds__(256, 1) void k_main(const float* __restrict__ x,
                                                 const void* __restrict__ lbl,
                                                 const float* __restrict__ W1w,
                                                 const float* __restrict__ W1b,
                                                 float* __restrict__ out) {
    extern __shared__ char sm[];
    uint32_t smb = smem_u32(sm);
    int tid = threadIdx.x;
    int wid = tid >> 5, lane = tid & 31;
    int wm = wid >> 2, wn = wid & 3;        // warp grid 2 x 4
    int m0 = blockIdx.x * 128;

    // ---- converter thread maps ----
    int arow = tid >> 1;                    // 0..127
    int akh  = (tid & 1) * 16;              // 0 / 16
    const float* aptr = x + (size_t)(m0 + arow) * DIN + akh;
    uint32_t a_st = (uint32_t)(arow * A_STRIDE + akh) * 2;   // byte offset
    const float* bptr = W1w + (size_t)tid * DIN;
    uint32_t b_st = (uint32_t)(tid * A_STRIDE) * 2;

    // ---- ldmatrix lane addressing ----
    int a_r = wm * 64 + (lane & 15);        // A row within 128
    int a_k = (lane >> 4) * 8;              // k sub-offset
    int b_r = wn * 64 + (lane & 7);         // B row within 256
    int b_k = ((lane >> 3) & 1) * 8;

    float acc[4][8][4];
#pragma unroll
    for (int i = 0; i < 4; ++i)
#pragma unroll
        for (int j = 0; j < 8; ++j)
#pragma unroll
            for (int q = 0; q < 4; ++q) acc[i][j][q] = 0.f;

    for (int k0 = 0; k0 < DIN; k0 += KC) {
        // ---- convert A [128 x 32] ----
#pragma unroll
        for (int q = 0; q < 4; ++q) {
            float4 v = *(const float4*)(aptr + k0 + 4 * q);
            uint2 hi, lo; split4(v, hi, lo);
            *(uint2*)(sm + SM_AH + a_st + 8 * q) = hi;
            *(uint2*)(sm + SM_AL + a_st + 8 * q) = lo;
        }
        // ---- convert B [256 x 32] ----
#pragma unroll
        for (int q = 0; q < 8; ++q) {
            float4 v = *(const float4*)(bptr + k0 + 4 * q);
            uint2 hi, lo; split4(v, hi, lo);
            *(uint2*)(sm + SM_BH + b_st + 8 * q) = hi;
            *(uint2*)(sm + SM_BL + b_st + 8 * q) = lo;
        }
        __syncthreads();

        // ---- MMA over the 32-k chunk (two k16 steps) ----
#pragma unroll
        for (int kk = 0; kk < KC; kk += 16) {
            uint32_t ah[4][4], al[4][4];
#pragma unroll
            for (int mi = 0; mi < 4; ++mi) {
                uint32_t off = (uint32_t)((a_r + mi * 16) * A_STRIDE + kk + a_k) * 2;
                ldsm_x4(smb + SM_AH + off, ah[mi]);
                ldsm_x4(smb + SM_AL + off, al[mi]);
            }
#pragma unroll
            for (int ni = 0; ni < 8; ++ni) {
                uint32_t boff = (uint32_t)((b_r + ni * 8) * A_STRIDE + kk + b_k) * 2;
                uint32_t bh[2], bl[2];
                ldsm_x2(smb + SM_BH + boff, bh);
                ldsm_x2(smb + SM_BL + boff, bl);
#pragma unroll
                for (int mi = 0; mi < 4; ++mi) {
                    mma_bf16(acc[mi][ni], ah[mi], bh);
                    mma_bf16(acc[mi][ni], ah[mi], bl);
                    mma_bf16(acc[mi][ni], al[mi], bh);
                }
            }
        }
        __syncthreads();
    }

    // ---- epilogue: + b1[n] + M2[label[m]][n] ----
    int is64 = g_lbl_is64;
    int nlo = (lane & 3) * 2;               // col pair within 8-wide tile
    int rbase = m0 + wm * 64 + (lane >> 2); // row for c0/c1

    // preload b1 pairs for this thread's 8 n-tiles
    float2 bb[8];
#pragma unroll
    for (int ni = 0; ni < 8; ++ni)
        bb[ni] = *(const float2*)(W1b + wn * 64 + ni * 8 + nlo);

#pragma unroll
    for (int mi = 0; mi < 4; ++mi) {
        int r0 = rbase + mi * 16;
        int r1 = r0 + 8;
        int c0 = load_label(lbl, r0, is64);
        int c1 = load_label(lbl, r1, is64);
        const float* m2r0 = g_M2 + (size_t)c0 * DOUT;
        const float* m2r1 = g_M2 + (size_t)c1 * DOUT;
        float* o0 = out + (size_t)r0 * DOUT;
        float* o1 = out + (size_t)r1 * DOUT;
#pragma unroll
        for (int ni = 0; ni < 8; ++ni) {
            int n = wn * 64 + ni * 8 + nlo;
            float2 mA = *(const float2*)(m2r0 + n);
            float2 mB = *(const float2*)(m2r1 + n);
            float2 vA, vB;
            vA.x = acc[mi][ni][0] + bb[ni].x + mA.x;
            vA.y = acc[mi][ni][1] + bb[ni].y + mA.y;
            vB.x = acc[mi][ni][2] + bb[ni].x + mB.x;
            vB.y = acc[mi][ni][3] + bb[ni].y + mB.y;
            *(float2*)(o0 + n) = vA;
            *(float2*)(o1 + n) = vB;
        }
    }
}

// ---------------- launch ----------------------------------------------------
extern "C" void kernel_launch(void* const* d_in, const int* in_sizes, int n_in,
                              void* d_out, int out_size) {
    const float* x   = (const float*)d_in[0];
    const void*  lbl = d_in[1];
    const float* W1w = (const float*)d_in[2];
    const float* W1b = (const float*)d_in[3];
    const float* W2w = (const float*)d_in[4];
    const float* W2b = (const float*)d_in[5];
    float* out = (float*)d_out;

    cudaFuncSetAttribute(k_main, cudaFuncAttributeMaxDynamicSharedMemorySize, SM_TOT);

    k_zero<<<512, 256>>>();
    k_detect<<<32, 256>>>((const int*)lbl);
    k_scatter<<<B_ROWS, 256>>>(x, lbl);
    k_total<<<dim3(16, 16), 256>>>();
    k_m2<<<dim3(4, 32), 256>>>(W2w, W2b);
    k_main<<<128, 256, SM_TOT>>>(x, lbl, W1w, W1b, out);
}